// round 2
// baseline (speedup 1.0000x reference)
#include <cuda_runtime.h>
#include <cstdint>

// Problem constants (fixed by the reference: B=32, C=3, H=512, W=512)
#define BB 32
#define CC 3
#define HH 512
#define WW 512
#define HWSZ (HH * WW)          // 262144
#define NPIX (BB * HWSZ)        // 8388608
#define PIX_PER_THREAD 2

// Bilinear flow-warp, matching torch F.grid_sample(align_corners=True) semantics
// as written in the reference:
//   i = row + 0.5*(H-1)*flow_y ; j = col + 0.5*(W-1)*flow_x
//   i1 = clip(floor(i),0,H-1); i2 = clip(i1+1,0,H-1); di = i - i1  (same for j)
//   q = lerp_j( lerp_i(q11,q21,di), lerp_i(q12,q22,di), dj )
//
// One thread handles 2 consecutive pixels (same batch; HW even) x all 3 channels.
__global__ __launch_bounds__(256) void flow_warp_kernel(
    const float* __restrict__ x,     // [B, C, H, W]
    const float* __restrict__ flow,  // [B, H, W, 2]
    float* __restrict__ out)         // [B, C, H, W]
{
    const int t = blockIdx.x * blockDim.x + threadIdx.x;
    const int pix = t * PIX_PER_THREAD;           // linear pixel index over B*H*W
    if (pix >= NPIX) return;

    const int b = pix >> 18;                      // pix / HWSZ (HWSZ = 2^18)
    const int p0 = pix & (HWSZ - 1);              // within-image linear index (even)

    // Coalesced float4 load: flow for 2 consecutive pixels
    const float4 f = *reinterpret_cast<const float4*>(flow + (size_t)pix * 2);

    const float* __restrict__ xb = x + (size_t)b * CC * HWSZ;
    float* __restrict__ ob = out + (size_t)b * CC * HWSZ;

    // Per-pixel results, [channel][pixel-in-pair]
    float res[CC][PIX_PER_THREAD];

    #pragma unroll
    for (int k = 0; k < PIX_PER_THREAD; ++k) {
        const int p = p0 + k;
        const int row = p >> 9;                   // p / WW   (WW = 2^9)
        const int col = p & (WW - 1);

        const float fx = (k == 0) ? f.x : f.z;
        const float fy = (k == 0) ? f.y : f.w;

        // pixel-space sample coordinates
        const float i = (float)row + 0.5f * (float)(HH - 1) * fy;
        const float j = (float)col + 0.5f * (float)(WW - 1) * fx;

        // clamp order exactly as reference
        float i1f = floorf(i);
        i1f = fminf(fmaxf(i1f, 0.0f), (float)(HH - 1));
        const float i2f = fminf(i1f + 1.0f, (float)(HH - 1));
        float j1f = floorf(j);
        j1f = fminf(fmaxf(j1f, 0.0f), (float)(WW - 1));
        const float j2f = fminf(j1f + 1.0f, (float)(WW - 1));

        const int i1 = (int)i1f, i2 = (int)i2f;
        const int j1 = (int)j1f, j2 = (int)j2f;

        const float di = i - i1f;
        const float dj = j - j1f;

        const int idx11 = i1 * WW + j1;
        const int idx12 = i1 * WW + j2;
        const int idx21 = i2 * WW + j1;
        const int idx22 = i2 * WW + j2;

        #pragma unroll
        for (int c = 0; c < CC; ++c) {
            const float* __restrict__ xc = xb + c * HWSZ;
            const float q11 = __ldg(xc + idx11);
            const float q12 = __ldg(xc + idx12);
            const float q21 = __ldg(xc + idx21);
            const float q22 = __ldg(xc + idx22);
            // two-stage lerp (same association as reference)
            const float qa = q11 * (1.0f - di) + q21 * di;
            const float qb = q12 * (1.0f - di) + q22 * di;
            res[c][k] = qa * (1.0f - dj) + qb * dj;
        }
    }

    // Coalesced 8B stores per channel (p0 even -> aligned)
    #pragma unroll
    for (int c = 0; c < CC; ++c) {
        float2 v;
        v.x = res[c][0];
        v.y = res[c][1];
        *reinterpret_cast<float2*>(ob + c * HWSZ + p0) = v;
    }
}

extern "C" void kernel_launch(void* const* d_in, const int* in_sizes, int n_in,
                              void* d_out, int out_size) {
    const float* x = (const float*)d_in[0];
    const float* flow = (const float*)d_in[1];
    float* out = (float*)d_out;

    const int threads = 256;
    const int total_threads = NPIX / PIX_PER_THREAD;   // 4194304
    const int blocks = (total_threads + threads - 1) / threads;  // 16384
    flow_warp_kernel<<<blocks, threads>>>(x, flow, out);
}

// round 3
// speedup vs baseline: 1.2182x; 1.2182x over previous
#include <cuda_runtime.h>
#include <cstdint>

// Problem constants (fixed by the reference: B=32, C=3, H=512, W=512)
#define BB 32
#define CC 3
#define HH 512
#define WW 512
#define HWSZ (HH * WW)          // 262144

// 2D tiling: block = 256 threads = 8 warps.
// Warp w handles rows [warp*4 .. warp*4+3] of a 32x32 tile; lane = column.
// Tile gives vertical L1 reuse (taps jitter +-~12 rows); float4 gathers merge
// the (j1, j1+1) tap pair into one LDG.128 that never crosses the row.
__global__ __launch_bounds__(256) void flow_warp_kernel(
    const float* __restrict__ x,     // [B, C, H, W]
    const float* __restrict__ flow,  // [B, H, W, 2]
    float* __restrict__ out)         // [B, C, H, W]
{
    const int lane = threadIdx.x & 31;
    const int warp = threadIdx.x >> 5;
    const int col  = blockIdx.x * 32 + lane;
    const int row0 = blockIdx.y * 32 + warp * 4;
    const int b    = blockIdx.z;

    const float* __restrict__ xb = x   + (size_t)b * CC * HWSZ;
    float* __restrict__       ob = out + (size_t)b * CC * HWSZ;
    const float* __restrict__ fb = flow + (size_t)b * HWSZ * 2;

    #pragma unroll
    for (int rr = 0; rr < 4; ++rr) {
        const int row = row0 + rr;
        const int p   = row * WW + col;

        const float2 f = *reinterpret_cast<const float2*>(fb + (size_t)p * 2);

        // pixel-space sample coordinates (identity grid + flow)
        const float i = (float)row + 0.5f * (float)(HH - 1) * f.y;
        const float j = (float)col + 0.5f * (float)(WW - 1) * f.x;

        // clamp order exactly as reference
        float i1f = fminf(fmaxf(floorf(i), 0.0f), (float)(HH - 1));
        const float i2f = fminf(i1f + 1.0f, (float)(HH - 1));
        float j1f = fminf(fmaxf(floorf(j), 0.0f), (float)(WW - 1));

        const int i1 = (int)i1f, i2 = (int)i2f, j1 = (int)j1f;
        const float di = i - i1f;
        const float dj = j - j1f;

        const int e4 = j1 & ~3;           // 16B-aligned, e4+3 <= 511 always
        const int o  = j1 & 3;
        const bool needx = (o == 3) && (j1 < WW - 1);  // j1+1 not in the float4

        const int r1 = i1 * WW;
        const int r2 = i2 * WW;

        #pragma unroll
        for (int c = 0; c < CC; ++c) {
            const float* __restrict__ xc = xb + c * HWSZ;

            const float4 v1 = __ldg(reinterpret_cast<const float4*>(xc + r1 + e4));
            const float4 v2 = __ldg(reinterpret_cast<const float4*>(xc + r2 + e4));

            // q11 = element o of v1; q21 = element o of v2
            const float q11 = (o >= 2) ? ((o == 3) ? v1.w : v1.z)
                                       : ((o == 1) ? v1.y : v1.x);
            const float q21 = (o >= 2) ? ((o == 3) ? v2.w : v2.z)
                                       : ((o == 1) ? v2.y : v2.x);
            // q12 = element o+1 (o<=2), or v.w if j1==511 (j2 clamps to j1)
            float q12 = (o == 0) ? v1.y : ((o == 1) ? v1.z : v1.w);
            float q22 = (o == 0) ? v2.y : ((o == 1) ? v2.z : v2.w);
            if (needx) {
                q12 = __ldg(xc + r1 + j1 + 1);
                q22 = __ldg(xc + r2 + j1 + 1);
            }

            // two-stage lerp (same association as reference)
            const float qa = q11 * (1.0f - di) + q21 * di;
            const float qb = q12 * (1.0f - di) + q22 * di;
            ob[c * HWSZ + p] = qa * (1.0f - dj) + qb * dj;
        }
    }
}

extern "C" void kernel_launch(void* const* d_in, const int* in_sizes, int n_in,
                              void* d_out, int out_size) {
    const float* x = (const float*)d_in[0];
    const float* flow = (const float*)d_in[1];
    float* out = (float*)d_out;

    dim3 grid(WW / 32, HH / 32, BB);   // 16 x 16 x 32
    flow_warp_kernel<<<grid, 256>>>(x, flow, out);
}